// round 2
// baseline (speedup 1.0000x reference)
#include <cuda_runtime.h>
#include <cuda_bf16.h>
#include <cstdint>

// Problem constants
#define NN 8
#define AA 256
#define HH 128
#define WW 128
#define CC 19
#define CP1 20
#define HT 1024
#define WT 1024

// Device scratch (no cudaMalloc allowed)
__device__ float gSums[CP1 * AA];
__device__ float gSq[CP1 * AA];
__device__ float gCount[32];
__device__ float gS[CP1 * CC];
__device__ unsigned char gLab[NN * HH * WW];
__device__ int gIs64;

// ---------------------------------------------------------------------------
// K0: zero the per-class accumulators AND detect target dtype (int32 vs int64).
// For an int64 label array (values in [0,19)), every odd 32-bit word is the
// zero high-word. For int32 labels, odd words are random labels, ~never all 0.
// Reads only the first 8192 words (< element count) -> safe for both dtypes.
// ---------------------------------------------------------------------------
__global__ void zero_detect_kernel(const int* __restrict__ tw) {
    __shared__ int anynz;
    int i = blockIdx.x * 256 + threadIdx.x;
    if (i < CP1 * AA) { gSums[i] = 0.f; gSq[i] = 0.f; }
    if (i < 32) gCount[i] = 0.f;

    if (blockIdx.x == 0) {
        if (threadIdx.x == 0) anynz = 0;
        __syncthreads();
        int v = 0;
        #pragma unroll
        for (int k = 0; k < 16; k++) {
            int idx = threadIdx.x * 16 + k;          // 0..4095
            v |= tw[idx * 2 + 1];                    // word idx <= 8191
        }
        if (v != 0) atomicOr(&anynz, 1);
        __syncthreads();
        if (threadIdx.x == 0) gIs64 = (anynz == 0) ? 1 : 0;
    }
}

// ---------------------------------------------------------------------------
// K1: per-(n,h,a_half) block.
//  - downsample labels (target[n, h*8, w*8]) with runtime dtype dispatch
//  - counting-sort the 128 pixels of this row by class (smem)
//  - stage features f[a][w] into smem (coalesced), stride 129
//  - thread t owns feature column a; walks pixels in sorted order with running
//    register accumulators, flushing on class change -> no atomics in hot loop
//  - one coalesced atomicAdd pass to global at the end
// ---------------------------------------------------------------------------
__global__ void stats_kernel(const float* __restrict__ features,
                             const int* __restrict__ tw) {
    extern __shared__ float sm[];
    float* buf  = sm;                          // [128][129]
    float* accS = sm + 128 * 129;              // [20][128]
    float* accQ = accS + CP1 * 128;            // [20][128]
    int*   cnt  = (int*)(accQ + CP1 * 128);    // [20]
    int*   offs = cnt + CP1;                   // [20]
    int*   slab = offs + CP1;                  // [128]
    int*   sw   = slab + 128;                  // [128]

    const int t    = threadIdx.x;      // 0..127
    const int half = blockIdx.x;       // 0/1 -> a range
    const int h    = blockIdx.y;
    const int n    = blockIdx.z;
    const int aBase = half * 128;

    #pragma unroll
    for (int c = 0; c < CP1; c++) { accS[c * 128 + t] = 0.f; accQ[c * 128 + t] = 0.f; }
    if (t < CP1) cnt[t] = 0;

    // label for pixel w=t (nearest-neighbor downsample), dtype-dispatched
    long long eidx = ((long long)n * HT + (long long)h * 8) * WT + (long long)t * 8;
    int raw = gIs64 ? tw[eidx * 2] : tw[eidx];
    int l0 = (raw == 255) ? 0 : raw;
    if (l0 < 0) l0 = 0;
    if (l0 > CP1 - 1) l0 = CP1 - 1;

    __syncthreads();
    atomicAdd(&cnt[l0], 1);

    const float* fptr = features + ((size_t)(n * AA + aBase)) * (HH * WW) + (size_t)h * WW + t;
    __syncthreads();
    if (t == 0) {
        int run = 0;
        #pragma unroll
        for (int c = 0; c < CP1; c++) { offs[c] = run; run += cnt[c]; }
    }
    __syncthreads();
    {
        int pos = atomicAdd(&offs[l0], 1);
        slab[pos] = l0;
        sw[pos]   = t;
    }

    // coalesced load of 128 a-rows x 128 w into buf (stride 129)
    #pragma unroll 16
    for (int r = 0; r < 128; r++) {
        buf[r * 129 + t] = fptr[(size_t)r * (HH * WW)];
    }
    __syncthreads();

    // sorted-run accumulation: thread t owns column a = aBase + t
    {
        float s = 0.f, q = 0.f;
        int run = slab[0];
        #pragma unroll 8
        for (int i = 0; i < 128; i++) {
            int l = slab[i];              // broadcast LDS, uniform
            if (l != run) {               // uniform, rare
                accS[run * 128 + t] += s;
                accQ[run * 128 + t] += q;
                s = 0.f; q = 0.f; run = l;
            }
            float f = buf[t * 129 + sw[i]];   // stride-129, conflict-free
            s += f;
            q += f * f;
        }
        accS[run * 128 + t] += s;
        accQ[run * 128 + t] += q;
    }
    __syncthreads();

    #pragma unroll
    for (int c = 0; c < CP1; c++) {
        atomicAdd(&gSums[c * AA + aBase + t], accS[c * 128 + t]);
        atomicAdd(&gSq[c * AA + aBase + t],   accQ[c * 128 + t]);
    }
    if (aBase == 0) {
        if (t < CP1) atomicAdd(&gCount[t], (float)cnt[t]);
        gLab[((size_t)n * HH + h) * WW + t] = (unsigned char)(raw & 0xFF);
    }
}

// ---------------------------------------------------------------------------
// K2: single block. new_cov[20][256], then S[l][c] = ratio * sum_a ncov[l,a] *
// (W[c,a]-W[l,a])^2  (the whole per-pixel matmul collapses to this table).
// ---------------------------------------------------------------------------
__global__ void cov_s_kernel(const float* __restrict__ fc,
                             const float* __restrict__ Ave,
                             const float* __restrict__ CoV,
                             const float* __restrict__ Amount,
                             const int* __restrict__ ratio_p) {
    __shared__ float ncov[CP1 * AA];
    __shared__ float Wsm[CC * AA];
    const int t = threadIdx.x;         // 256 threads, t == feature index a

    #pragma unroll
    for (int c = 0; c < CC; c++) Wsm[c * AA + t] = fc[c * AA + t];

    #pragma unroll
    for (int c = 0; c < CP1; c++) {
        float cntv = gCount[c];
        float cntc = (cntv == 0.f) ? 1.f : cntv;
        float sum  = gSums[c * AA + t];
        float sq   = gSq[c * AA + t];
        float ave  = sum / cntc;
        float var  = sq / cntc - ave * ave;
        float denom = cntv + Amount[c];
        float wcv  = (denom > 0.f) ? (cntv / denom) : 0.f;
        float d    = Ave[c * AA + t] - ave;
        ncov[c * AA + t] = CoV[c * AA + t] * (1.f - wcv) + var * wcv
                         + wcv * (1.f - wcv) * d * d;
    }
    __syncthreads();

    float r = (float)(*ratio_p);       // low 4 LE bytes: correct for i32 & i64
    int wid = t >> 5, lane = t & 31;
    for (int p = wid; p < CC * CC; p += 8) {
        int l = p / CC, c = p % CC;
        float s = 0.f;
        #pragma unroll
        for (int k = 0; k < 8; k++) {
            int a = lane + k * 32;
            float d = Wsm[c * AA + a] - Wsm[l * AA + a];
            s += ncov[l * AA + a] * d * d;
        }
        #pragma unroll
        for (int o = 16; o; o >>= 1) s += __shfl_down_sync(0xffffffffu, s, o);
        if (lane == 0) gS[l * CC + c] = r * s;
    }
}

// ---------------------------------------------------------------------------
// K3: out[n,c,h,w] = y[n,c,h,w] + 0.5 * S[l(n,h,w), c] * (l != 255)
// ---------------------------------------------------------------------------
__global__ void aug_kernel(const float* __restrict__ y, float* __restrict__ out) {
    __shared__ float Ssm[CP1];
    const int bid = blockIdx.x;                 // over N * C * (H/4)
    const int t = threadIdx.x;                  // 512
    const int n   = bid / (CC * (HH / 4));
    const int rem = bid % (CC * (HH / 4));
    const int c   = rem / (HH / 4);
    const int h4  = rem % (HH / 4);

    if (t < CP1) Ssm[t] = (t < CC) ? gS[t * CC + c] : 0.f;
    __syncthreads();

    const int h = h4 * 4 + (t >> 7);
    const int w = t & 127;
    int li = gLab[((size_t)n * HH + h) * WW + w];
    size_t oidx = (((size_t)n * CC + c) * HH + h) * WW + w;
    float v = y[oidx];
    if (li != 255) {
        int ls = (li > CP1 - 1) ? (CP1 - 1) : li;
        v += 0.5f * Ssm[ls];
    }
    out[oidx] = v;
}

// ---------------------------------------------------------------------------
extern "C" void kernel_launch(void* const* d_in, const int* in_sizes, int n_in,
                              void* d_out, int out_size) {
    const float* features = (const float*)d_in[0];
    const float* y        = (const float*)d_in[1];
    const float* fc       = (const float*)d_in[2];
    const float* Ave      = (const float*)d_in[3];
    const float* CoV      = (const float*)d_in[4];
    const float* Amount   = (const float*)d_in[5];
    const int*   target_w = (const int*)d_in[6];   // int32 or int64 (probed)
    const int*   ratio    = (const int*)d_in[7];
    float*       out      = (float*)d_out;

    // K0: zero accumulators + dtype probe
    zero_detect_kernel<<<(CP1 * AA + 255) / 256, 256>>>(target_w);

    // K1: stats
    const int smem1 = (128 * 129 + 2 * CP1 * 128) * 4 + (2 * CP1 + 2 * 128) * 4;
    cudaFuncSetAttribute(stats_kernel, cudaFuncAttributeMaxDynamicSharedMemorySize, smem1);
    dim3 g1(2, HH, NN);
    stats_kernel<<<g1, 128, smem1>>>(features, target_w);

    // K2: covariance update + S table
    cov_s_kernel<<<1, 256>>>(fc, Ave, CoV, Amount, ratio);

    // K3: output
    aug_kernel<<<NN * CC * (HH / 4), 512>>>(y, out);
}

// round 3
// speedup vs baseline: 2.2251x; 2.2251x over previous
#include <cuda_runtime.h>
#include <cuda_bf16.h>
#include <cstdint>

// Problem constants
#define NN 8
#define AA 256
#define HH 128
#define WW 128
#define CC 19
#define CP1 20
#define HT 1024
#define WT 1024
#define RPB 8              // h-rows per stats block

// Device scratch (no cudaMalloc allowed)
__device__ float gSums[CP1 * AA];
__device__ float gSq[CP1 * AA];
__device__ float gCount[32];
__device__ float gS[CP1 * CC];
__device__ unsigned char gLab[NN * HH * WW];
__device__ int gIs64;

// ---------------------------------------------------------------------------
// K0: zero accumulators + detect target dtype (int32 vs int64).
// int64 labels in [0,19): every odd 32-bit word is a zero high-word.
// ---------------------------------------------------------------------------
__global__ void zero_detect_kernel(const int* __restrict__ tw) {
    __shared__ int anynz;
    int i = blockIdx.x * 256 + threadIdx.x;
    if (i < CP1 * AA) { gSums[i] = 0.f; gSq[i] = 0.f; }
    if (i < 32) gCount[i] = 0.f;

    if (blockIdx.x == 0) {
        if (threadIdx.x == 0) anynz = 0;
        __syncthreads();
        int v = 0;
        #pragma unroll
        for (int k = 0; k < 16; k++) {
            int idx = threadIdx.x * 16 + k;          // 0..4095
            v |= tw[idx * 2 + 1];                    // word idx <= 8191 (safe)
        }
        if (v != 0) atomicOr(&anynz, 1);
        __syncthreads();
        if (threadIdx.x == 0) gIs64 = (anynz == 0) ? 1 : 0;
    }
}

// ---------------------------------------------------------------------------
// K1: stats. Block = (a_half, h-block of 8 rows, n). 256 threads, 2 CTA/SM.
// Per h-row: counting sort of 128 labels; stage 128a x 128w feature tile to
// smem (coalesced, stride-129 conflict-free transposed reads); two 128-thread
// groups each walk 64 sorted pixels with running register accumulators,
// flushing to private smem bins on class change. ONE global atomic flush per
// block (8 rows amortized) -> 1.3M atomics total instead of 10.5M.
// ---------------------------------------------------------------------------
__global__ __launch_bounds__(256, 2)
void stats_kernel(const float* __restrict__ features,
                  const int* __restrict__ tw) {
    extern __shared__ float sm[];
    float* buf  = sm;                            // [128][129]
    float* accS = sm + 128 * 129;                // [2][20][128]
    float* accQ = accS + 2 * CP1 * 128;          // [2][20][128]
    int*   cnt  = (int*)(accQ + 2 * CP1 * 128);  // [20]
    int*   offs = cnt + CP1;                     // [20]
    int*   ccnt = offs + CP1;                    // [20] block-accumulated counts
    int*   slab = ccnt + CP1;                    // [128]
    int*   sw   = slab + 128;                    // [128]

    const int t  = threadIdx.x;        // 0..255
    const int g  = t >> 7;             // pixel group 0/1
    const int tl = t & 127;            // owned feature column (within half)
    const int half = blockIdx.x;
    const int hb   = blockIdx.y;       // 0..15
    const int n    = blockIdx.z;
    const int aBase = half * 128;
    const int is64 = gIs64;

    for (int i = t; i < 2 * CP1 * 128; i += 256) { accS[i] = 0.f; accQ[i] = 0.f; }
    if (t < CP1) ccnt[t] = 0;

    const float* fbase = features + ((size_t)(n * AA + aBase)) * (HH * WW);

    for (int ch = 0; ch < RPB; ch++) {
        const int h = hb * RPB + ch;

        // labels into registers; zero cnt
        int raw = 0, l0 = 0;
        if (t < 128) {
            long long eidx = ((long long)n * HT + (long long)h * 8) * WT
                           + (long long)t * 8;
            raw = is64 ? tw[eidx * 2] : tw[eidx];
            l0 = (raw == 255) ? 0 : raw;
            if (l0 < 0) l0 = 0;
            if (l0 > CP1 - 1) l0 = CP1 - 1;
        }
        if (t < CP1) cnt[t] = 0;
        __syncthreads();                       // prev accum done; cnt zeroed

        if (t < 128) atomicAdd(&cnt[l0], 1);

        // stage feature tile (buf free now); overlaps with sort syncs
        {
            const float* fr = fbase + (size_t)h * WW + tl;
            #pragma unroll 16
            for (int j = 0; j < 64; j++) {
                int r = j * 2 + g;
                buf[r * 129 + tl] = fr[(size_t)r * (HH * WW)];
            }
        }
        __syncthreads();                       // cnt final

        if (t == 0) {
            int run = 0;
            #pragma unroll
            for (int c = 0; c < CP1; c++) { offs[c] = run; run += cnt[c]; }
        }
        if (half == 0 && t < CP1) ccnt[t] += cnt[t];
        __syncthreads();                       // offs ready

        if (t < 128) {
            int pos = atomicAdd(&offs[l0], 1);
            slab[pos] = l0;
            sw[pos]   = t;
            if (half == 0)
                gLab[((size_t)n * HH + h) * WW + t] = (unsigned char)(raw & 0xFF);
        }
        __syncthreads();                       // slab/sw + buf ready

        // sorted-run accumulation: group g -> sorted pixels [64g, 64g+64)
        {
            float s = 0.f, q = 0.f;
            const int base = g * 64;
            int run = slab[base];
            #pragma unroll 4
            for (int i = 0; i < 64; i++) {
                int l = slab[base + i];
                int w = sw[base + i];
                float f = buf[tl * 129 + w];     // stride-129, conflict-free
                if (l != run) {                  // warp-uniform, rare
                    accS[(g * CP1 + run) * 128 + tl] += s;
                    accQ[(g * CP1 + run) * 128 + tl] += q;
                    s = 0.f; q = 0.f; run = l;
                }
                s += f;
                q += f * f;
            }
            accS[(g * CP1 + run) * 128 + tl] += s;
            accQ[(g * CP1 + run) * 128 + tl] += q;
        }
        // no trailing sync; next iteration's first sync covers the hazard
    }
    __syncthreads();

    // single flush per block: merge the two groups, coalesced atomics
    for (int i = t; i < CP1 * 128; i += 256) {
        int c = i >> 7, al = i & 127;
        float vs = accS[c * 128 + al] + accS[(CP1 + c) * 128 + al];
        float vq = accQ[c * 128 + al] + accQ[(CP1 + c) * 128 + al];
        atomicAdd(&gSums[c * AA + aBase + al], vs);
        atomicAdd(&gSq[c * AA + aBase + al],   vq);
    }
    if (half == 0 && t < CP1) atomicAdd(&gCount[t], (float)ccnt[t]);
}

// ---------------------------------------------------------------------------
// K2: single block, 1024 threads. new_cov[20][256], then
// S[l][c] = ratio * sum_a ncov[l,a] * (W[c,a]-W[l,a])^2
// ---------------------------------------------------------------------------
__global__ void cov_s_kernel(const float* __restrict__ fc,
                             const float* __restrict__ Ave,
                             const float* __restrict__ CoV,
                             const float* __restrict__ Amount,
                             const int* __restrict__ ratio_p) {
    __shared__ float ncov[CP1 * AA];   // 20KB
    __shared__ float Wsm[CC * AA];     // 19KB
    const int t = threadIdx.x;         // 0..1023

    for (int i = t; i < CC * AA; i += 1024) Wsm[i] = fc[i];

    #pragma unroll
    for (int i = t; i < CP1 * AA; i += 1024) {
        int c = i >> 8;
        float cntv = gCount[c];
        float cntc = (cntv == 0.f) ? 1.f : cntv;
        float ave  = gSums[i] / cntc;
        float var  = gSq[i] / cntc - ave * ave;
        float denom = cntv + Amount[c];
        float wcv  = (denom > 0.f) ? (cntv / denom) : 0.f;
        float d    = Ave[i] - ave;
        ncov[i] = CoV[i] * (1.f - wcv) + var * wcv + wcv * (1.f - wcv) * d * d;
    }
    __syncthreads();

    float r = (float)(*ratio_p);       // low 4 LE bytes: correct for i32 & i64
    int wid = t >> 5, lane = t & 31;
    for (int p = wid; p < CC * CC; p += 32) {
        int l = p / CC, c = p % CC;
        float s = 0.f;
        #pragma unroll
        for (int k = 0; k < 8; k++) {
            int a = lane + k * 32;
            float d = Wsm[c * AA + a] - Wsm[l * AA + a];
            s += ncov[l * AA + a] * d * d;
        }
        #pragma unroll
        for (int o = 16; o; o >>= 1) s += __shfl_down_sync(0xffffffffu, s, o);
        if (lane == 0) gS[l * CC + c] = r * s;
    }
}

// ---------------------------------------------------------------------------
// K3: out[n,c,h,w] = y[n,c,h,w] + 0.5 * S[l(n,h,w), c] * (l != 255)
// one block per (n,c) -> 152 blocks = one wave; float4/uchar4 vectorized
// ---------------------------------------------------------------------------
__global__ __launch_bounds__(512, 2)
void aug_kernel(const float* __restrict__ y, float* __restrict__ out) {
    __shared__ float Ssm[CP1];
    const int t = threadIdx.x;                 // 0..511
    const int n = blockIdx.x / CC;
    const int c = blockIdx.x % CC;

    if (t < CP1) Ssm[t] = (t < CC) ? (0.5f * gS[t * CC + c]) : 0.f;
    __syncthreads();

    const float4* y4 = (const float4*)(y + ((size_t)n * CC + c) * (HH * WW));
    float4*       o4 = (float4*)(out + ((size_t)n * CC + c) * (HH * WW));
    const uchar4* l4 = (const uchar4*)(gLab + (size_t)n * (HH * WW));

    #pragma unroll 8
    for (int i = t; i < (HH * WW) / 4; i += 512) {
        uchar4 lb = l4[i];
        float4 v  = y4[i];
        if (lb.x != 255) v.x += Ssm[lb.x];
        if (lb.y != 255) v.y += Ssm[lb.y];
        if (lb.z != 255) v.z += Ssm[lb.z];
        if (lb.w != 255) v.w += Ssm[lb.w];
        o4[i] = v;
    }
}

// ---------------------------------------------------------------------------
extern "C" void kernel_launch(void* const* d_in, const int* in_sizes, int n_in,
                              void* d_out, int out_size) {
    const float* features = (const float*)d_in[0];
    const float* y        = (const float*)d_in[1];
    const float* fc       = (const float*)d_in[2];
    const float* Ave      = (const float*)d_in[3];
    const float* CoV      = (const float*)d_in[4];
    const float* Amount   = (const float*)d_in[5];
    const int*   target_w = (const int*)d_in[6];   // int32 or int64 (probed)
    const int*   ratio    = (const int*)d_in[7];
    float*       out      = (float*)d_out;

    // K0: zero accumulators + dtype probe
    zero_detect_kernel<<<(CP1 * AA + 255) / 256, 256>>>(target_w);

    // K1: stats  (smem: buf + 2x(accS,accQ) + sort arrays)
    const int smem1 = (128 * 129 + 4 * CP1 * 128) * 4 + (3 * CP1 + 2 * 128) * 4;
    cudaFuncSetAttribute(stats_kernel, cudaFuncAttributeMaxDynamicSharedMemorySize, smem1);
    dim3 g1(2, HH / RPB, NN);
    stats_kernel<<<g1, 256, smem1>>>(features, target_w);

    // K2: covariance update + S table
    cov_s_kernel<<<1, 1024>>>(fc, Ave, CoV, Amount, ratio);

    // K3: output
    aug_kernel<<<NN * CC, 512>>>(y, out);
}

// round 4
// speedup vs baseline: 2.6559x; 1.1936x over previous
#include <cuda_runtime.h>
#include <cuda_bf16.h>
#include <cstdint>

// Problem constants
#define NN 8
#define AA 256
#define HH 128
#define WW 128
#define CC 19
#define CP1 20
#define HT 1024
#define WT 1024
#define RPB 4              // h-rows per stats block
#define ACOLS 64           // a-columns per stats block

// Device scratch (no cudaMalloc allowed)
__device__ float gSums[CP1 * AA];
__device__ float gSq[CP1 * AA];
__device__ float gCount[32];
__device__ float gS[CP1 * CC];
__device__ unsigned char gLab[NN * HH * WW];
__device__ int gLW[NN * HH * WW];     // per-row sorted (label<<8 | w)
__device__ int gIs64;

// ---------------------------------------------------------------------------
// K0: zero accumulators + detect target dtype (int32 vs int64).
// int64 labels in [0,19): every odd 32-bit word is a zero high-word.
// ---------------------------------------------------------------------------
__global__ void zero_detect_kernel(const int* __restrict__ tw) {
    __shared__ int anynz;
    int i = blockIdx.x * 256 + threadIdx.x;
    if (i < CP1 * AA) { gSums[i] = 0.f; gSq[i] = 0.f; }
    if (i < 32) gCount[i] = 0.f;

    if (blockIdx.x == 0) {
        if (threadIdx.x == 0) anynz = 0;
        __syncthreads();
        int v = 0;
        #pragma unroll
        for (int k = 0; k < 16; k++) {
            int idx = threadIdx.x * 16 + k;          // 0..4095
            v |= tw[idx * 2 + 1];                    // word idx <= 8191 (safe)
        }
        if (v != 0) atomicOr(&anynz, 1);
        __syncthreads();
        if (threadIdx.x == 0) gIs64 = (anynz == 0) ? 1 : 0;
    }
}

// ---------------------------------------------------------------------------
// K0b: per-row label fetch + counting sort. One block per (n,h) row.
// Writes gLW (sorted packed label|w), gLab (raw bytes for aug), gCount.
// ---------------------------------------------------------------------------
__global__ void sort_kernel(const int* __restrict__ tw) {
    __shared__ int cnt[CP1];
    __shared__ int offs[CP1];
    const int t = threadIdx.x;          // 0..127 (w)
    const int row = blockIdx.x;         // n*HH + h
    const int n = row >> 7;
    const int h = row & 127;

    long long eidx = ((long long)n * HT + (long long)h * 8) * WT + (long long)t * 8;
    int raw = gIs64 ? tw[eidx * 2] : tw[eidx];
    int l0 = (raw == 255) ? 0 : raw;
    if (l0 < 0) l0 = 0;
    if (l0 > CP1 - 1) l0 = CP1 - 1;

    if (t < CP1) cnt[t] = 0;
    __syncthreads();
    atomicAdd(&cnt[l0], 1);
    gLab[(size_t)row * WW + t] = (unsigned char)(raw & 0xFF);
    __syncthreads();
    if (t == 0) {
        int run = 0;
        #pragma unroll
        for (int c = 0; c < CP1; c++) { offs[c] = run; run += cnt[c]; }
    }
    if (t < CP1) atomicAdd(&gCount[t], (float)cnt[t]);
    __syncthreads();
    int pos = atomicAdd(&offs[l0], 1);
    gLW[(size_t)row * WW + pos] = (l0 << 8) | t;
}

// ---------------------------------------------------------------------------
// K1: stats. Block = (a-quarter of 64, h-block of 4 rows, n). 256 threads,
// ~75KB smem -> 3 CTA/SM. Per row: 32 floats/thread staged GMEM->regs->smem
// (conflict-free), with the next row's 32 LDGs issued BEFORE the accumulation
// phase so DRAM latency overlaps the smem-bound accum. Accum: 4 groups of 2
// warps each walk 32 pre-sorted pixels with running register accumulators,
// flushing to private smem bins on class change. One atomic flush per block.
// ---------------------------------------------------------------------------
__global__ __launch_bounds__(256, 3)
void stats_kernel(const float* __restrict__ features) {
    __shared__ float buf[ACOLS * 129];               // 33 KB
    __shared__ float accS[4 * CP1 * ACOLS];          // 20 KB
    __shared__ float accQ[4 * CP1 * ACOLS];          // 20 KB
    __shared__ int   lwsm[RPB * 128];                // 2 KB

    const int t   = threadIdx.x;        // 0..255
    const int g   = t >> 6;             // pixel group 0..3
    const int tl  = t & 63;             // owned a-column within quarter
    const int w32 = t & 31;             // staging lane (w)
    const int rg  = t >> 5;             // staging row group 0..7
    const int q   = blockIdx.x;         // a-quarter 0..3
    const int hb  = blockIdx.y;         // 0..31
    const int n   = blockIdx.z;
    const int aBase = q * ACOLS;

    // zero accumulators + preload sorted lw for the 4 rows
    #pragma unroll
    for (int i = t; i < 4 * CP1 * ACOLS; i += 256) { accS[i] = 0.f; accQ[i] = 0.f; }
    {
        const int lwbase = (n * HH + hb * RPB) * 128;
        #pragma unroll
        for (int i = t; i < RPB * 128; i += 256) lwsm[i] = gLW[lwbase + i];
    }

    const float* fbase = features + ((size_t)(n * AA + aBase)) * (HH * WW)
                       + (size_t)(hb * RPB) * WW;

    // prologue: load row 0 into registers (8 rows x 4 w-chunks per thread)
    float pf[32];
    #pragma unroll
    for (int k = 0; k < 8; k++)
        #pragma unroll
        for (int m = 0; m < 4; m++)
            pf[k * 4 + m] = fbase[(size_t)(rg + 8 * k) * (HH * WW) + w32 + 32 * m];

    #pragma unroll
    for (int ch = 0; ch < RPB; ch++) {
        __syncthreads();   // buf free (prev accum done); lwsm/acc ready on ch=0

        // store current row tile to smem (conflict-free: bank = rg+w32+? distinct)
        #pragma unroll
        for (int k = 0; k < 8; k++)
            #pragma unroll
            for (int m = 0; m < 4; m++)
                buf[(rg + 8 * k) * 129 + w32 + 32 * m] = pf[k * 4 + m];

        // issue next row's loads NOW; results awaited at next iteration's STS,
        // overlapping the accumulation phase below
        if (ch + 1 < RPB) {
            #pragma unroll
            for (int k = 0; k < 8; k++)
                #pragma unroll
                for (int m = 0; m < 4; m++)
                    pf[k * 4 + m] = fbase[(size_t)(rg + 8 * k) * (HH * WW)
                                          + (ch + 1) * WW + w32 + 32 * m];
        }
        __syncthreads();   // buf filled

        // sorted-run accumulation: group g -> sorted pixels [32g, 32g+32)
        {
            const int* lwr = lwsm + ch * 128 + g * 32;
            int lw0 = lwr[0];
            int run = lw0 >> 8;
            float s = 0.f, sq = 0.f;
            #pragma unroll 8
            for (int i = 0; i < 32; i++) {
                int lw = lwr[i];                  // uniform LDS (broadcast)
                int w  = lw & 255;
                int l  = lw >> 8;
                float f = buf[tl * 129 + w];      // conflict-free
                if (l != run) {                   // group-uniform branch
                    accS[(g * CP1 + run) * ACOLS + tl] += s;
                    accQ[(g * CP1 + run) * ACOLS + tl] += sq;
                    s = 0.f; sq = 0.f; run = l;
                }
                s  += f;
                sq += f * f;
            }
            accS[(g * CP1 + run) * ACOLS + tl] += s;
            accQ[(g * CP1 + run) * ACOLS + tl] += sq;
        }
    }
    __syncthreads();

    // merge 4 groups, single coalesced atomic flush
    #pragma unroll
    for (int i = t; i < CP1 * ACOLS; i += 256) {
        int c = i >> 6, al = i & 63;
        float vs = 0.f, vq = 0.f;
        #pragma unroll
        for (int gg = 0; gg < 4; gg++) {
            vs += accS[(gg * CP1 + c) * ACOLS + al];
            vq += accQ[(gg * CP1 + c) * ACOLS + al];
        }
        atomicAdd(&gSums[c * AA + aBase + al], vs);
        atomicAdd(&gSq[c * AA + aBase + al],   vq);
    }
}

// ---------------------------------------------------------------------------
// K2: single block, 1024 threads. new_cov[20][256], then
// S[l][c] = ratio * sum_a ncov[l,a] * (W[c,a]-W[l,a])^2
// ---------------------------------------------------------------------------
__global__ void cov_s_kernel(const float* __restrict__ fc,
                             const float* __restrict__ Ave,
                             const float* __restrict__ CoV,
                             const float* __restrict__ Amount,
                             const int* __restrict__ ratio_p) {
    __shared__ float ncov[CP1 * AA];
    __shared__ float Wsm[CC * AA];
    const int t = threadIdx.x;         // 0..1023

    for (int i = t; i < CC * AA; i += 1024) Wsm[i] = fc[i];

    #pragma unroll
    for (int i = t; i < CP1 * AA; i += 1024) {
        int c = i >> 8;
        float cntv = gCount[c];
        float cntc = (cntv == 0.f) ? 1.f : cntv;
        float ave  = gSums[i] / cntc;
        float var  = gSq[i] / cntc - ave * ave;
        float denom = cntv + Amount[c];
        float wcv  = (denom > 0.f) ? (cntv / denom) : 0.f;
        float d    = Ave[i] - ave;
        ncov[i] = CoV[i] * (1.f - wcv) + var * wcv + wcv * (1.f - wcv) * d * d;
    }
    __syncthreads();

    float r = (float)(*ratio_p);       // low 4 LE bytes: correct for i32 & i64
    int wid = t >> 5, lane = t & 31;
    for (int p = wid; p < CC * CC; p += 32) {
        int l = p / CC, c = p % CC;
        float s = 0.f;
        #pragma unroll
        for (int k = 0; k < 8; k++) {
            int a = lane + k * 32;
            float d = Wsm[c * AA + a] - Wsm[l * AA + a];
            s += ncov[l * AA + a] * d * d;
        }
        #pragma unroll
        for (int o = 16; o; o >>= 1) s += __shfl_down_sync(0xffffffffu, s, o);
        if (lane == 0) gS[l * CC + c] = r * s;
    }
}

// ---------------------------------------------------------------------------
// K3: out[n,c,h,w] = y[n,c,h,w] + 0.5 * S[l(n,h,w), c] * (l != 255)
// 4 blocks per (n,c) -> 608 blocks, 256 threads, float4/uchar4
// ---------------------------------------------------------------------------
__global__ __launch_bounds__(256, 4)
void aug_kernel(const float* __restrict__ y, float* __restrict__ out) {
    __shared__ float Ssm[CP1];
    const int t = threadIdx.x;                 // 0..255
    const int bq = blockIdx.x & 3;             // h-quarter
    const int nc = blockIdx.x >> 2;
    const int n = nc / CC;
    const int c = nc % CC;

    if (t < CP1) Ssm[t] = (t < CC) ? (0.5f * gS[t * CC + c]) : 0.f;
    __syncthreads();

    const size_t plane = ((size_t)n * CC + c) * (HH * WW);
    const int qoff = bq * (HH * WW / 16);      // in float4 units
    const float4* y4 = (const float4*)(y + plane) + qoff;
    float4*       o4 = (float4*)(out + plane) + qoff;
    const uchar4* l4 = (const uchar4*)(gLab + (size_t)n * (HH * WW)) + qoff;

    #pragma unroll 4
    for (int i = t; i < (HH * WW) / 16; i += 256) {
        uchar4 lb = l4[i];
        float4 v  = y4[i];
        if (lb.x != 255) v.x += Ssm[lb.x];
        if (lb.y != 255) v.y += Ssm[lb.y];
        if (lb.z != 255) v.z += Ssm[lb.z];
        if (lb.w != 255) v.w += Ssm[lb.w];
        o4[i] = v;
    }
}

// ---------------------------------------------------------------------------
extern "C" void kernel_launch(void* const* d_in, const int* in_sizes, int n_in,
                              void* d_out, int out_size) {
    const float* features = (const float*)d_in[0];
    const float* y        = (const float*)d_in[1];
    const float* fc       = (const float*)d_in[2];
    const float* Ave      = (const float*)d_in[3];
    const float* CoV      = (const float*)d_in[4];
    const float* Amount   = (const float*)d_in[5];
    const int*   target_w = (const int*)d_in[6];   // int32 or int64 (probed)
    const int*   ratio    = (const int*)d_in[7];
    float*       out      = (float*)d_out;

    // K0: zero accumulators + dtype probe
    zero_detect_kernel<<<(CP1 * AA + 255) / 256, 256>>>(target_w);

    // K0b: per-row label sort
    sort_kernel<<<NN * HH, 128>>>(target_w);

    // K1: stats
    dim3 g1(4, HH / RPB, NN);
    stats_kernel<<<g1, 256>>>(features);

    // K2: covariance update + S table
    cov_s_kernel<<<1, 1024>>>(fc, Ave, CoV, Amount, ratio);

    // K3: output
    aug_kernel<<<NN * CC * 4, 256>>>(y, out);
}